// round 13
// baseline (speedup 1.0000x reference)
#include <cuda_runtime.h>
#include <cuda_fp16.h>
#include <cstdint>

// ---------------- problem constants ----------------
#define NWIN    4096
#define NTOK    49
#define HID     384
#define NHEAD   12
#define DHEAD   32
#define MTOT    (NWIN*NTOK)          // 200704
#define QSCALE  0.17677669529663687f // 32^-0.5

#define NBH     (NWIN*NHEAD)         // 49152
#define QK_STRIDE (49*40)
#define VT_STRIDE (32*72)

#define X_ELEMS  ((size_t)MTOT * HID)      // 77070336
#define W1_ELEMS (1152 * 384)              // 442368
#define W2_ELEMS (384 * 384)               // 147456

// GEMM stage: Ah[128x40] Al Bh[96x40] Bl (halves, 80B row stride)
#define STG_AL 10240
#define STG_BH 20480
#define STG_BL 28160
#define STG_BYTES 35840
#define GEMM_SMEM (2 * STG_BYTES)          // 71680

// ---------------- device scratch ----------------
__device__ __half g_xh[X_ELEMS],  g_xl[X_ELEMS];    // x pre-split
__device__ __half g_aoh[X_ELEMS], g_aol[X_ELEMS];   // attn out pre-split
__device__ __half g_qwh[W1_ELEMS], g_qwl[W1_ELEMS]; // qkv_w pre-split
__device__ __half g_fwh[W2_ELEMS], g_fwl[W2_ELEMS]; // fc_w pre-split
// q/k pre-split planar [w,h][t*40+d]; v pre-split transposed [w,h][d*72+t]
// (vt pad cols 49..71 never written -> stay zero from .bss = NaN guard)
__device__ __half g_qh[(size_t)NBH * QK_STRIDE];
__device__ __half g_ql[(size_t)NBH * QK_STRIDE];
__device__ __half g_kh[(size_t)NBH * QK_STRIDE];
__device__ __half g_kl[(size_t)NBH * QK_STRIDE];
__device__ __half g_vth[(size_t)NBH * VT_STRIDE];
__device__ __half g_vtl[(size_t)NBH * VT_STRIDE];
__device__ float g_bias[NHEAD * NTOK * NTOK];

// ---------------- helpers ----------------
__device__ __forceinline__ void mma_f16(float c[4], const uint32_t a[4], const uint32_t b[2]) {
    asm volatile(
        "mma.sync.aligned.m16n8k16.row.col.f32.f16.f16.f32 "
        "{%0,%1,%2,%3}, {%4,%5,%6,%7}, {%8,%9}, {%0,%1,%2,%3};\n"
        : "+f"(c[0]), "+f"(c[1]), "+f"(c[2]), "+f"(c[3])
        : "r"(a[0]), "r"(a[1]), "r"(a[2]), "r"(a[3]),
          "r"(b[0]), "r"(b[1]));
}

__device__ __forceinline__ void ldsm4(uint32_t r[4], uint32_t addr) {
    asm volatile("ldmatrix.sync.aligned.m8n8.x4.shared.b16 {%0,%1,%2,%3}, [%4];\n"
                 : "=r"(r[0]), "=r"(r[1]), "=r"(r[2]), "=r"(r[3]) : "r"(addr));
}

__device__ __forceinline__ uint32_t ld_h2(const __half* p) {
    return *reinterpret_cast<const uint32_t*>(p);
}

__device__ __forceinline__ void cp16(uint32_t smem_addr, const void* gptr) {
    asm volatile("cp.async.cg.shared.global [%0], [%1], 16;\n"
                 :: "r"(smem_addr), "l"(gptr));
}

// ---------------- K-1: split fp32 -> hi/lo fp16 ----------------
__global__ void split_kernel(const float* __restrict__ src,
                             __half* __restrict__ hi, __half* __restrict__ lo,
                             size_t n) {
    size_t i = ((size_t)blockIdx.x * 256 + threadIdx.x) * 4;
    if (i + 3 < n) {
        float4 v = *reinterpret_cast<const float4*>(src + i);
        __half2 h0 = __floats2half2_rn(v.x, v.y);
        __half2 h1 = __floats2half2_rn(v.z, v.w);
        float2 f0 = __half22float2(h0), f1 = __half22float2(h1);
        __half2 l0 = __floats2half2_rn(v.x - f0.x, v.y - f0.y);
        __half2 l1 = __floats2half2_rn(v.z - f1.x, v.w - f1.y);
        *reinterpret_cast<__half2*>(hi + i)     = h0;
        *reinterpret_cast<__half2*>(hi + i + 2) = h1;
        *reinterpret_cast<__half2*>(lo + i)     = l0;
        *reinterpret_cast<__half2*>(lo + i + 2) = l1;
    }
}

// ---------------- GEMM mainloop: C[128x96] = A * B^T, cp.async 2-stage ----------------
__device__ __forceinline__ void gemm_issue(const __half* __restrict__ Ahg,
                                           const __half* __restrict__ Alg,
                                           const __half* __restrict__ Bhg,
                                           const __half* __restrict__ Blg,
                                           int m0, int n0, int s, uint32_t sbase) {
    const int tid = threadIdx.x;
    const uint32_t stg = sbase + (s & 1) * STG_BYTES;
    const int k0 = s * 32;
    #pragma unroll
    for (int it = 0; it < 7; it++) {
        int c = tid + it * 256;                  // 0..1791
        uint32_t dst;
        const __half* src;
        if (c < 1024) {
            int a = c & 511, row = a >> 2, cc = a & 3;
            dst = stg + (c < 512 ? 0u : (uint32_t)STG_AL) + row * 80 + cc * 16;
            src = (c < 512 ? Ahg : Alg) + (size_t)(m0 + row) * 384 + k0 + cc * 8;
        } else {
            int a = c - 1024;
            int w = (a >= 384);
            if (w) a -= 384;
            int row = a >> 2, cc = a & 3;
            dst = stg + (w ? (uint32_t)STG_BL : (uint32_t)STG_BH) + row * 80 + cc * 16;
            src = (w ? Blg : Bhg) + (size_t)(n0 + row) * 384 + k0 + cc * 8;
        }
        cp16(dst, src);
    }
    asm volatile("cp.async.commit_group;\n");
}

__device__ __forceinline__ void run_gemm(const __half* __restrict__ Ahg,
                                         const __half* __restrict__ Alg,
                                         const __half* __restrict__ Bhg,
                                         const __half* __restrict__ Blg,
                                         int m0, int n0,
                                         char* smem, float acc[2][6][4]) {
    const int tid  = threadIdx.x;
    const int lane = tid & 31;
    const int wid  = tid >> 5;
    const int wm   = wid & 3;
    const int wn   = wid >> 2;
    const uint32_t sbase = (uint32_t)__cvta_generic_to_shared(smem);

    const int aRow = wm * 32 + (lane & 15);
    const int aCol = (lane >> 4) << 3;
    const int bRow = wn * 48 + (lane & 7) + ((lane & 16) >> 1);
    const int bCol = lane & 8;

    gemm_issue(Ahg, Alg, Bhg, Blg, m0, n0, 0, sbase);

    for (int s = 0; s < 12; s++) {
        if (s + 1 < 12) {
            gemm_issue(Ahg, Alg, Bhg, Blg, m0, n0, s + 1, sbase);
            asm volatile("cp.async.wait_group 1;\n" ::: "memory");
        } else {
            asm volatile("cp.async.wait_group 0;\n" ::: "memory");
        }
        __syncthreads();

        const uint32_t stg = sbase + (s & 1) * STG_BYTES;
        #pragma unroll
        for (int ks = 0; ks < 32; ks += 16) {
            uint32_t ah[2][4], al[2][4], bh4[3][4], bl4[3][4];
            #pragma unroll
            for (int mt = 0; mt < 2; mt++) {
                const uint32_t aoff = (uint32_t)(((aRow + mt * 16) * 40 + ks + aCol) * 2);
                ldsm4(ah[mt], stg + aoff);
                ldsm4(al[mt], stg + STG_AL + aoff);
            }
            #pragma unroll
            for (int ntp = 0; ntp < 3; ntp++) {
                const uint32_t boff = (uint32_t)(((bRow + ntp * 16) * 40 + ks + bCol) * 2);
                ldsm4(bh4[ntp], stg + STG_BH + boff);
                ldsm4(bl4[ntp], stg + STG_BL + boff);
            }
            #pragma unroll
            for (int mt = 0; mt < 2; mt++)
                #pragma unroll
                for (int nt = 0; nt < 6; nt++) {
                    const uint32_t* bh = &bh4[nt >> 1][(nt & 1) * 2];
                    const uint32_t* bl = &bl4[nt >> 1][(nt & 1) * 2];
                    mma_f16(acc[mt][nt], ah[mt], bh);
                    mma_f16(acc[mt][nt], ah[mt], bl);
                    mma_f16(acc[mt][nt], al[mt], bh);
                }
        }
        __syncthreads();
    }
}

// ---------------- K0: dense relative position bias ----------------
__global__ void bias_kernel(const float* __restrict__ table, const int* __restrict__ ridx) {
    int e = blockIdx.x * 256 + threadIdx.x;
    if (e < NHEAD * NTOK * NTOK) {
        int h = e / (NTOK * NTOK);
        int r = e - h * (NTOK * NTOK);
        g_bias[e] = table[ridx[r] * NHEAD + h];
    }
}

// ---------------- K1: QKV projection + split scatter ----------------
__global__ void __launch_bounds__(256) qkv_kernel(const float* __restrict__ qkv_b) {
    extern __shared__ char smem[];
    float acc[2][6][4];
    #pragma unroll
    for (int a = 0; a < 2; a++)
        #pragma unroll
        for (int b = 0; b < 6; b++)
            #pragma unroll
            for (int c = 0; c < 4; c++) acc[a][b][c] = 0.f;

    const int n0 = blockIdx.x * 96;
    const int m0 = blockIdx.y * 128;
    run_gemm(g_xh, g_xl, g_qwh, g_qwl, m0, n0, smem, acc);

    // stage C (stages dead now)
    float* cst = reinterpret_cast<float*>(smem);
    const int lane = threadIdx.x & 31, wid = threadIdx.x >> 5;
    const int wm = wid & 3, wn = wid >> 2;
    const int rr = lane >> 2, c2 = (lane & 3) << 1;
    #pragma unroll
    for (int mt = 0; mt < 2; mt++)
        #pragma unroll
        for (int nt = 0; nt < 6; nt++) {
            int row = wm * 32 + mt * 16 + rr;
            int col = wn * 48 + nt * 8 + c2;
            cst[row * 96 + col]           = acc[mt][nt][0];
            cst[row * 96 + col + 1]       = acc[mt][nt][1];
            cst[(row + 8) * 96 + col]     = acc[mt][nt][2];
            cst[(row + 8) * 96 + col + 1] = acc[mt][nt][3];
        }
    __syncthreads();

    const int h = blockIdx.x;
    for (int e = threadIdx.x; e < 128 * 64; e += 256) {
        int dd  = e & 31;
        int sp  = (e >> 5) & 1;
        int row = e >> 6;
        int col = dd * 3 + sp;
        float val = cst[row * 96 + col] + qkv_b[n0 + col];
        if (sp == 0) val *= QSCALE;
        __half hi = __float2half_rn(val);
        __half lo = __float2half_rn(val - __half2float(hi));
        int m = m0 + row;
        int ww = m / 49;
        int t  = m - ww * 49;
        size_t o = (size_t)(ww * NHEAD + h) * QK_STRIDE + t * 40 + dd;
        if (sp == 0) { g_qh[o] = hi; g_ql[o] = lo; }
        else         { g_kh[o] = hi; g_kl[o] = lo; }
    }
    for (int e = threadIdx.x; e < 128 * 32; e += 256) {
        int row = e & 127;
        int dd  = e >> 7;
        int col = dd * 3 + 2;
        float val = cst[row * 96 + col] + qkv_b[n0 + col];
        __half hi = __float2half_rn(val);
        __half lo = __float2half_rn(val - __half2float(hi));
        int m = m0 + row;
        int ww = m / 49;
        int t  = m - ww * 49;
        size_t o = (size_t)(ww * NHEAD + h) * VT_STRIDE + dd * 72 + t;
        g_vth[o] = hi;
        g_vtl[o] = lo;
    }
}

// ---------------- K2: per-(window,head) attention via fp16-split MMA ----------------
struct AttnSmem {
    union {
        struct {
            __half Qh[64 * 40];
            __half Ql[64 * 40];
            __half Kh[64 * 40];
            __half Kl[64 * 40];
        } qk;
        struct {
            __half Ph[64 * 72];
            __half Pl[64 * 72];
        } p;
    } u;
    __half Vth[32 * 72];
    __half Vtl[32 * 72];
    float  sc[64 * 57];
};

__global__ void __launch_bounds__(128) attn_kernel() {
    const int bid = blockIdx.x;        // ww*NHEAD + h
    const int h   = bid % NHEAD;
    const int ww  = bid / NHEAD;

    __shared__ AttnSmem s;

    const int tid = threadIdx.x, lane = tid & 31, wm = tid >> 5;
    const int rr  = lane >> 2;
    const int qoff = (lane & 3) << 1;

    {
        const uint32_t smQ = (uint32_t)__cvta_generic_to_shared(s.u.qk.Qh);
        const uint32_t smV = (uint32_t)__cvta_generic_to_shared(s.Vth);
        const char* gqh = (const char*)g_qh + (size_t)bid * (QK_STRIDE * 2);
        const char* gql = (const char*)g_ql + (size_t)bid * (QK_STRIDE * 2);
        const char* gkh = (const char*)g_kh + (size_t)bid * (QK_STRIDE * 2);
        const char* gkl = (const char*)g_kl + (size_t)bid * (QK_STRIDE * 2);
        const char* gvh = (const char*)g_vth + (size_t)bid * (VT_STRIDE * 2);
        const char* gvl = (const char*)g_vtl + (size_t)bid * (VT_STRIDE * 2);
        for (int e = tid; e < 245; e += 128) {
            cp16(smQ + e * 16,         gqh + e * 16);
            cp16(smQ + 5120 + e * 16,  gql + e * 16);
            cp16(smQ + 10240 + e * 16, gkh + e * 16);
            cp16(smQ + 15360 + e * 16, gkl + e * 16);
        }
        for (int e = tid; e < 288; e += 128) {
            cp16(smV + e * 16,        gvh + e * 16);
            cp16(smV + 4608 + e * 16, gvl + e * 16);
        }
        asm volatile("cp.async.commit_group;\n");
        asm volatile("cp.async.wait_group 0;\n" ::: "memory");
    }
    __syncthreads();

    // ---- scores ----
    {
        float acc[7][4];
        #pragma unroll
        for (int nt = 0; nt < 7; nt++)
            #pragma unroll
            for (int c = 0; c < 4; c++) acc[nt][c] = 0.f;

        #pragma unroll
        for (int kt = 0; kt < 32; kt += 16) {
            uint32_t ah[4], al[4];
            const int rb = wm * 16 + rr;
            const int cc = kt + qoff;
            ah[0] = ld_h2(&s.u.qk.Qh[rb * 40 + cc]);
            ah[1] = ld_h2(&s.u.qk.Qh[(rb + 8) * 40 + cc]);
            ah[2] = ld_h2(&s.u.qk.Qh[rb * 40 + cc + 8]);
            ah[3] = ld_h2(&s.u.qk.Qh[(rb + 8) * 40 + cc + 8]);
            al[0] = ld_h2(&s.u.qk.Ql[rb * 40 + cc]);
            al[1] = ld_h2(&s.u.qk.Ql[(rb + 8) * 40 + cc]);
            al[2] = ld_h2(&s.u.qk.Ql[rb * 40 + cc + 8]);
            al[3] = ld_h2(&s.u.qk.Ql[(rb + 8) * 40 + cc + 8]);
            #pragma unroll
            for (int nt = 0; nt < 7; nt++) {
                const int nb = nt * 8 + rr;
                uint32_t bh[2], bl[2];
                bh[0] = ld_h2(&s.u.qk.Kh[nb * 40 + cc]);
                bh[1] = ld_h2(&s.u.qk.Kh[nb * 40 + cc + 8]);
                bl[0] = ld_h2(&s.u.qk.Kl[nb * 40 + cc]);
                bl[1] = ld_h2(&s.u.qk.Kl[nb * 40 + cc + 8]);
                mma_f16(acc[nt], ah, bh);
                mma_f16(acc[nt], ah, bl);
                mma_f16(acc[nt], al, bh);
            }
        }
        const int r0 = wm * 16 + rr;
        #pragma unroll
        for (int nt = 0; nt < 7; nt++) {
            const int c = nt * 8 + qoff;
            s.sc[r0 * 57 + c]           = acc[nt][0];
            s.sc[r0 * 57 + c + 1]       = acc[nt][1];
            s.sc[(r0 + 8) * 57 + c]     = acc[nt][2];
            s.sc[(r0 + 8) * 57 + c + 1] = acc[nt][3];
        }
    }
    __syncthreads();

    // ---- softmax (+bias), write P split fp16 ----
    const float* bias = &g_bias[h * (NTOK * NTOK)];
    for (int i = wm; i < NTOK; i += 4) {
        const int j2 = 32 + lane;
        const bool v2 = (j2 < NTOK);
        float s0 = s.sc[i * 57 + lane] + bias[i * 49 + lane];
        float s1 = v2 ? (s.sc[i * 57 + j2] + bias[i * 49 + j2]) : -3.0e38f;
        float mx = fmaxf(s0, s1);
        #pragma unroll
        for (int o = 16; o; o >>= 1) mx = fmaxf(mx, __shfl_xor_sync(0xffffffffu, mx, o));
        float p0 = expf(s0 - mx);
        float p1 = v2 ? expf(s1 - mx) : 0.f;
        float sum = p0 + p1;
        #pragma unroll
        for (int o = 16; o; o >>= 1) sum += __shfl_xor_sync(0xffffffffu, sum, o);
        float inv = 1.f / sum;
        p0 *= inv;
        p1 = v2 ? p1 * inv : 0.f;
        {
            __half hi = __float2half_rn(p0);
            __half lo = __float2half_rn(p0 - __half2float(hi));
            s.u.p.Ph[i * 72 + lane] = hi;
            s.u.p.Pl[i * 72 + lane] = lo;
            __half hi1 = __float2half_rn(p1);
            __half lo1 = __float2half_rn(p1 - __half2float(hi1));
            s.u.p.Ph[i * 72 + j2] = hi1;
            s.u.p.Pl[i * 72 + j2] = lo1;
        }
    }
    __syncthreads();

    // ---- PV ----
    {
        float acc[4][4];
        #pragma unroll
        for (int nt = 0; nt < 4; nt++)
            #pragma unroll
            for (int c = 0; c < 4; c++) acc[nt][c] = 0.f;

        #pragma unroll
        for (int kt = 0; kt < 64; kt += 16) {
            uint32_t ah[4], al[4];
            const int rb = wm * 16 + rr;
            const int cc = kt + qoff;
            ah[0] = ld_h2(&s.u.p.Ph[rb * 72 + cc]);
            ah[1] = ld_h2(&s.u.p.Ph[(rb + 8) * 72 + cc]);
            ah[2] = ld_h2(&s.u.p.Ph[rb * 72 + cc + 8]);
            ah[3] = ld_h2(&s.u.p.Ph[(rb + 8) * 72 + cc + 8]);
            al[0] = ld_h2(&s.u.p.Pl[rb * 72 + cc]);
            al[1] = ld_h2(&s.u.p.Pl[(rb + 8) * 72 + cc]);
            al[2] = ld_h2(&s.u.p.Pl[rb * 72 + cc + 8]);
            al[3] = ld_h2(&s.u.p.Pl[(rb + 8) * 72 + cc + 8]);
            #pragma unroll
            for (int nt = 0; nt < 4; nt++) {
                const int nb = nt * 8 + rr;
                uint32_t bh[2], bl[2];
                bh[0] = ld_h2(&s.Vth[nb * 72 + cc]);
                bh[1] = ld_h2(&s.Vth[nb * 72 + cc + 8]);
                bl[0] = ld_h2(&s.Vtl[nb * 72 + cc]);
                bl[1] = ld_h2(&s.Vtl[nb * 72 + cc + 8]);
                mma_f16(acc[nt], ah, bh);
                mma_f16(acc[nt], ah, bl);
                mma_f16(acc[nt], al, bh);
            }
        }
        // write attn output pre-split for fc
        const int r0 = wm * 16 + rr;
        #pragma unroll
        for (int nt = 0; nt < 4; nt++) {
            const int d = nt * 8 + qoff;
            #pragma unroll
            for (int half = 0; half < 2; half++) {
                int r = r0 + half * 8;
                if (r < NTOK) {
                    float a0 = acc[nt][half * 2], a1 = acc[nt][half * 2 + 1];
                    __half2 h2 = __floats2half2_rn(a0, a1);
                    float2 f = __half22float2(h2);
                    __half2 l2 = __floats2half2_rn(a0 - f.x, a1 - f.y);
                    size_t o = ((size_t)ww * NTOK + r) * HID + h * DHEAD + d;
                    *reinterpret_cast<__half2*>(&g_aoh[o]) = h2;
                    *reinterpret_cast<__half2*>(&g_aol[o]) = l2;
                }
            }
        }
    }
}

// ---------------- K3: output projection ----------------
__global__ void __launch_bounds__(256) fc_kernel(const float* __restrict__ fc_b,
                                                 float* __restrict__ out) {
    extern __shared__ char smem[];
    float acc[2][6][4];
    #pragma unroll
    for (int a = 0; a < 2; a++)
        #pragma unroll
        for (int b = 0; b < 6; b++)
            #pragma unroll
            for (int c = 0; c < 4; c++) acc[a][b][c] = 0.f;

    const int n0 = blockIdx.x * 96;
    const int m0 = blockIdx.y * 128;
    run_gemm(g_aoh, g_aol, g_fwh, g_fwl, m0, n0, smem, acc);

    const int lane = threadIdx.x & 31, wid = threadIdx.x >> 5;
    const int wm = wid & 3, wn = wid >> 2;
    const int rr = lane >> 2, c2 = (lane & 3) << 1;
    #pragma unroll
    for (int mt = 0; mt < 2; mt++)
        #pragma unroll
        for (int nt = 0; nt < 6; nt++) {
            int row = m0 + wm * 32 + mt * 16 + rr;
            int col = n0 + wn * 48 + nt * 8 + c2;
            float b0 = fc_b[col], b1 = fc_b[col + 1];
            float2 v0 = make_float2(acc[mt][nt][0] + b0, acc[mt][nt][1] + b1);
            float2 v1 = make_float2(acc[mt][nt][2] + b0, acc[mt][nt][3] + b1);
            *reinterpret_cast<float2*>(&out[(size_t)row * 384 + col])       = v0;
            *reinterpret_cast<float2*>(&out[(size_t)(row + 8) * 384 + col]) = v1;
        }
}

// ---------------- launch ----------------
extern "C" void kernel_launch(void* const* d_in, const int* in_sizes, int n_in,
                              void* d_out, int out_size) {
    const float* x    = (const float*)d_in[0];
    const float* tbl  = (const float*)d_in[1];
    const float* qw   = (const float*)d_in[2];
    const float* qb   = (const float*)d_in[3];
    const float* fw   = (const float*)d_in[4];
    const float* fb   = (const float*)d_in[5];
    const int*   ridx = (const int*)d_in[6];
    float* out = (float*)d_out;

    cudaFuncSetAttribute(qkv_kernel, cudaFuncAttributeMaxDynamicSharedMemorySize, GEMM_SMEM);
    cudaFuncSetAttribute(fc_kernel,  cudaFuncAttributeMaxDynamicSharedMemorySize, GEMM_SMEM);

    __half *xh, *xl, *qwh, *qwl, *fwh, *fwl;
    cudaGetSymbolAddress((void**)&xh,  g_xh);
    cudaGetSymbolAddress((void**)&xl,  g_xl);
    cudaGetSymbolAddress((void**)&qwh, g_qwh);
    cudaGetSymbolAddress((void**)&qwl, g_qwl);
    cudaGetSymbolAddress((void**)&fwh, g_fwh);
    cudaGetSymbolAddress((void**)&fwl, g_fwl);

    split_kernel<<<(unsigned)((X_ELEMS / 4 + 255) / 256), 256>>>(x, xh, xl, X_ELEMS);
    split_kernel<<<(W1_ELEMS / 4 + 255) / 256, 256>>>(qw, qwh, qwl, W1_ELEMS);
    split_kernel<<<(W2_ELEMS / 4 + 255) / 256, 256>>>(fw, fwh, fwl, W2_ELEMS);
    bias_kernel<<<(NHEAD * NTOK * NTOK + 255) / 256, 256>>>(tbl, ridx);
    qkv_kernel<<<dim3(NHEAD, MTOT / 128), 256, GEMM_SMEM>>>(qb);
    attn_kernel<<<NWIN * NHEAD, 128>>>();
    fc_kernel<<<dim3(HID / 96, MTOT / 128), 256, GEMM_SMEM>>>(fb, out);
}

// round 14
// speedup vs baseline: 1.2340x; 1.2340x over previous
#include <cuda_runtime.h>
#include <cuda_fp16.h>
#include <cstdint>

// ---------------- problem constants ----------------
#define NWIN    4096
#define NTOK    49
#define HID     384
#define NHEAD   12
#define DHEAD   32
#define MTOT    (NWIN*NTOK)          // 200704
#define QSCALE  0.17677669529663687f // 32^-0.5

#define NBH     (NWIN*NHEAD)         // 49152
#define QK_STRIDE (49*40)            // halves per (w,h) planar q/k array
#define VT_STRIDE (32*72)            // halves per (w,h) transposed v array

// ---------------- device scratch ----------------
// q/k stored pre-split planar hi/lo in attn's smem layout [t*40+d].
// v stored pre-split, pre-transposed [d*72+t]; pad cols 49..71 are NEVER
// written -> remain zero from .bss init (NaN guard for PV pads).
__device__ __half g_qh[(size_t)NBH * QK_STRIDE];
__device__ __half g_ql[(size_t)NBH * QK_STRIDE];
__device__ __half g_kh[(size_t)NBH * QK_STRIDE];
__device__ __half g_kl[(size_t)NBH * QK_STRIDE];
__device__ __half g_vth[(size_t)NBH * VT_STRIDE];
__device__ __half g_vtl[(size_t)NBH * VT_STRIDE];
__device__ float g_ao[(size_t)MTOT * HID];   // attention output [m][h*32+d]
__device__ float g_bias[NHEAD * NTOK * NTOK];

// ---------------- shared memory layout for GEMM kernels ----------------
// 2-term split: A kept as hi+lo, B kept hi-only.
struct SmemGemm {
    __half Ah[128 * 40];   // 10240 B
    __half Al[128 * 40];   // 10240 B
    __half Bh[96 * 40];    //  7680 B
};
union SmemU {
    SmemGemm g;
    float    c[128 * 96];  // 49152 B (C staging)
};

// ---------------- mma.sync m16n8k16 fp16 -> fp32 ----------------
__device__ __forceinline__ void mma_f16(float c[4], const uint32_t a[4], const uint32_t b[2]) {
    asm volatile(
        "mma.sync.aligned.m16n8k16.row.col.f32.f16.f16.f32 "
        "{%0,%1,%2,%3}, {%4,%5,%6,%7}, {%8,%9}, {%0,%1,%2,%3};\n"
        : "+f"(c[0]), "+f"(c[1]), "+f"(c[2]), "+f"(c[3])
        : "r"(a[0]), "r"(a[1]), "r"(a[2]), "r"(a[3]),
          "r"(b[0]), "r"(b[1]));
}

__device__ __forceinline__ void ldsm4(uint32_t r[4], uint32_t addr) {
    asm volatile("ldmatrix.sync.aligned.m8n8.x4.shared.b16 {%0,%1,%2,%3}, [%4];\n"
                 : "=r"(r[0]), "=r"(r[1]), "=r"(r[2]), "=r"(r[3]) : "r"(addr));
}

__device__ __forceinline__ uint32_t ld_h2(const __half* p) {
    return *reinterpret_cast<const uint32_t*>(p);
}

__device__ __forceinline__ void split_store(__half* hi, __half* lo, float a, float b) {
    __half2 h, l;
    h.x = __float2half_rn(a); l.x = __float2half_rn(a - __half2float(h.x));
    h.y = __float2half_rn(b); l.y = __float2half_rn(b - __half2float(h.y));
    *reinterpret_cast<__half2*>(hi) = h;
    *reinterpret_cast<__half2*>(lo) = l;
}

__device__ __forceinline__ void hi_store(__half* hi, float a, float b) {
    *reinterpret_cast<__half2*>(hi) = __floats2half2_rn(a, b);
}

__device__ __forceinline__ void cp16(uint32_t smem_addr, const void* gptr) {
    asm volatile("cp.async.cg.shared.global [%0], [%1], 16;\n"
                 :: "r"(smem_addr), "l"(gptr));
}

// ---------------- shared GEMM mainloop (K1/K3): C[128x96] = A * B^T ----------------
// 2-term fp16 split: C = A_hi*B_hi + A_lo*B_hi  (B_lo dropped; rel err ~3e-4)
__device__ __forceinline__ void run_gemm(const float* __restrict__ A,
                                         const float* __restrict__ B,
                                         int m0, int n0,
                                         SmemGemm* sm, float acc[2][6][4]) {
    const int tid  = threadIdx.x;
    const int lane = tid & 31;
    const int wid  = tid >> 5;
    const int wm   = wid & 3;
    const int wn   = wid >> 2;
    const int lr   = tid >> 3;
    const int lc   = (tid & 7) << 2;

    const float* Abase = A + (size_t)(m0 + lr) * 384 + lc;
    const float* Bbase = B + (size_t)(n0 + lr) * 384 + lc;

    const uint32_t AhB = (uint32_t)__cvta_generic_to_shared(sm->Ah);
    const uint32_t AlB = (uint32_t)__cvta_generic_to_shared(sm->Al);
    const uint32_t BhB = (uint32_t)__cvta_generic_to_shared(sm->Bh);

    const int aRow = wm * 32 + (lane & 15);
    const int aCol = (lane >> 4) << 3;
    const int bRow = wn * 48 + (lane & 7) + ((lane & 16) >> 1);
    const int bCol = lane & 8;

    float4 ra[4], rb[3];
    #pragma unroll
    for (int p = 0; p < 4; p++)
        ra[p] = *reinterpret_cast<const float4*>(Abase + (size_t)p * 32 * 384);
    #pragma unroll
    for (int p = 0; p < 3; p++)
        rb[p] = *reinterpret_cast<const float4*>(Bbase + (size_t)p * 32 * 384);

    for (int k0 = 0; k0 < 384; k0 += 32) {
        __syncthreads();
        #pragma unroll
        for (int p = 0; p < 4; p++) {
            int row = lr + p * 32;
            split_store(&sm->Ah[row * 40 + lc],     &sm->Al[row * 40 + lc],     ra[p].x, ra[p].y);
            split_store(&sm->Ah[row * 40 + lc + 2], &sm->Al[row * 40 + lc + 2], ra[p].z, ra[p].w);
        }
        #pragma unroll
        for (int p = 0; p < 3; p++) {
            int row = lr + p * 32;
            hi_store(&sm->Bh[row * 40 + lc],     rb[p].x, rb[p].y);
            hi_store(&sm->Bh[row * 40 + lc + 2], rb[p].z, rb[p].w);
        }
        __syncthreads();

        if (k0 + 32 < 384) {
            #pragma unroll
            for (int p = 0; p < 4; p++)
                ra[p] = *reinterpret_cast<const float4*>(Abase + (size_t)p * 32 * 384 + k0 + 32);
            #pragma unroll
            for (int p = 0; p < 3; p++)
                rb[p] = *reinterpret_cast<const float4*>(Bbase + (size_t)p * 32 * 384 + k0 + 32);
        }

        #pragma unroll
        for (int ks = 0; ks < 32; ks += 16) {
            uint32_t ah[2][4], al[2][4], bh4[3][4];
            #pragma unroll
            for (int mt = 0; mt < 2; mt++) {
                const uint32_t aoff = (uint32_t)(((aRow + mt * 16) * 40 + ks + aCol) * 2);
                ldsm4(ah[mt], AhB + aoff);
                ldsm4(al[mt], AlB + aoff);
            }
            #pragma unroll
            for (int ntp = 0; ntp < 3; ntp++) {
                const uint32_t boff = (uint32_t)(((bRow + ntp * 16) * 40 + ks + bCol) * 2);
                ldsm4(bh4[ntp], BhB + boff);
            }
            #pragma unroll
            for (int mt = 0; mt < 2; mt++)
                #pragma unroll
                for (int nt = 0; nt < 6; nt++) {
                    const uint32_t* bh = &bh4[nt >> 1][(nt & 1) * 2];
                    mma_f16(acc[mt][nt], ah[mt], bh);
                    mma_f16(acc[mt][nt], al[mt], bh);
                }
        }
    }
}

// ---------------- K0: dense relative position bias ----------------
__global__ void bias_kernel(const float* __restrict__ table, const int* __restrict__ ridx) {
    int e = blockIdx.x * 256 + threadIdx.x;
    if (e < NHEAD * NTOK * NTOK) {
        int h = e / (NTOK * NTOK);
        int r = e - h * (NTOK * NTOK);
        g_bias[e] = table[ridx[r] * NHEAD + h];
    }
}

// ---------------- K1: QKV projection + split scatter ----------------
__global__ void __launch_bounds__(256) qkv_kernel(const float* __restrict__ x,
                                                  const float* __restrict__ qkv_w,
                                                  const float* __restrict__ qkv_b) {
    __shared__ SmemU sm;
    float acc[2][6][4];
    #pragma unroll
    for (int a = 0; a < 2; a++)
        #pragma unroll
        for (int b = 0; b < 6; b++)
            #pragma unroll
            for (int c = 0; c < 4; c++) acc[a][b][c] = 0.f;

    const int n0 = blockIdx.x * 96;
    const int m0 = blockIdx.y * 128;
    run_gemm(x, qkv_w, m0, n0, &sm.g, acc);
    __syncthreads();

    const int lane = threadIdx.x & 31, wid = threadIdx.x >> 5;
    const int wm = wid & 3, wn = wid >> 2;
    const int rr = lane >> 2, c2 = (lane & 3) << 1;
    #pragma unroll
    for (int mt = 0; mt < 2; mt++)
        #pragma unroll
        for (int nt = 0; nt < 6; nt++) {
            int row = wm * 32 + mt * 16 + rr;
            int col = wn * 48 + nt * 8 + c2;
            sm.c[row * 96 + col]           = acc[mt][nt][0];
            sm.c[row * 96 + col + 1]       = acc[mt][nt][1];
            sm.c[(row + 8) * 96 + col]     = acc[mt][nt][2];
            sm.c[(row + 8) * 96 + col + 1] = acc[mt][nt][3];
        }
    __syncthreads();

    const int h = blockIdx.x;
    // q,k: split hi/lo, planar layout [w,h][t*40+dd]; coalesced over dd
    for (int e = threadIdx.x; e < 128 * 64; e += 256) {
        int dd  = e & 31;
        int sp  = (e >> 5) & 1;
        int row = e >> 6;
        int col = dd * 3 + sp;
        float val = sm.c[row * 96 + col] + qkv_b[n0 + col];
        if (sp == 0) val *= QSCALE;
        __half hi = __float2half_rn(val);
        __half lo = __float2half_rn(val - __half2float(hi));
        int m = m0 + row;
        int ww = m / 49;
        int t  = m - ww * 49;
        size_t o = (size_t)(ww * NHEAD + h) * QK_STRIDE + t * 40 + dd;
        if (sp == 0) { g_qh[o] = hi; g_ql[o] = lo; }
        else         { g_kh[o] = hi; g_kl[o] = lo; }
    }
    // v: transposed layout [w,h][dd*72+t]; coalesced over t
    for (int e = threadIdx.x; e < 128 * 32; e += 256) {
        int row = e & 127;
        int dd  = e >> 7;
        int col = dd * 3 + 2;
        float val = sm.c[row * 96 + col] + qkv_b[n0 + col];
        __half hi = __float2half_rn(val);
        __half lo = __float2half_rn(val - __half2float(hi));
        int m = m0 + row;
        int ww = m / 49;
        int t  = m - ww * 49;
        size_t o = (size_t)(ww * NHEAD + h) * VT_STRIDE + dd * 72 + t;
        g_vth[o] = hi;
        g_vtl[o] = lo;
    }
}

// ---------------- K2: per-(window,head) attention via fp16-split MMA ----------------
// (unchanged from R12: full 3-term split, error contribution negligible)
struct AttnSmem {
    union {
        struct {
            __half Qh[64 * 40];
            __half Ql[64 * 40];
            __half Kh[64 * 40];
            __half Kl[64 * 40];
        } qk;
        struct {
            __half Ph[64 * 72];
            __half Pl[64 * 72];
        } p;
    } u;
    __half Vth[32 * 72];
    __half Vtl[32 * 72];
    float  sc[64 * 57];
};

__global__ void __launch_bounds__(128) attn_kernel() {
    const int bid = blockIdx.x;        // ww*NHEAD + h
    const int h   = bid % NHEAD;
    const int ww  = bid / NHEAD;

    __shared__ AttnSmem s;

    const int tid = threadIdx.x, lane = tid & 31, wm = tid >> 5;
    const int rr  = lane >> 2;
    const int qoff = (lane & 3) << 1;

    {
        const uint32_t smQ = (uint32_t)__cvta_generic_to_shared(s.u.qk.Qh);
        const uint32_t smV = (uint32_t)__cvta_generic_to_shared(s.Vth);
        const char* gqh = (const char*)g_qh + (size_t)bid * (QK_STRIDE * 2);
        const char* gql = (const char*)g_ql + (size_t)bid * (QK_STRIDE * 2);
        const char* gkh = (const char*)g_kh + (size_t)bid * (QK_STRIDE * 2);
        const char* gkl = (const char*)g_kl + (size_t)bid * (QK_STRIDE * 2);
        const char* gvh = (const char*)g_vth + (size_t)bid * (VT_STRIDE * 2);
        const char* gvl = (const char*)g_vtl + (size_t)bid * (VT_STRIDE * 2);
        for (int e = tid; e < 245; e += 128) {
            cp16(smQ + e * 16,         gqh + e * 16);
            cp16(smQ + 5120 + e * 16,  gql + e * 16);
            cp16(smQ + 10240 + e * 16, gkh + e * 16);
            cp16(smQ + 15360 + e * 16, gkl + e * 16);
        }
        for (int e = tid; e < 288; e += 128) {
            cp16(smV + e * 16,        gvh + e * 16);
            cp16(smV + 4608 + e * 16, gvl + e * 16);
        }
        asm volatile("cp.async.commit_group;\n");
        asm volatile("cp.async.wait_group 0;\n" ::: "memory");
    }
    __syncthreads();

    // ---- scores ----
    {
        float acc[7][4];
        #pragma unroll
        for (int nt = 0; nt < 7; nt++)
            #pragma unroll
            for (int c = 0; c < 4; c++) acc[nt][c] = 0.f;

        #pragma unroll
        for (int kt = 0; kt < 32; kt += 16) {
            uint32_t ah[4], al[4];
            const int rb = wm * 16 + rr;
            const int cc = kt + qoff;
            ah[0] = ld_h2(&s.u.qk.Qh[rb * 40 + cc]);
            ah[1] = ld_h2(&s.u.qk.Qh[(rb + 8) * 40 + cc]);
            ah[2] = ld_h2(&s.u.qk.Qh[rb * 40 + cc + 8]);
            ah[3] = ld_h2(&s.u.qk.Qh[(rb + 8) * 40 + cc + 8]);
            al[0] = ld_h2(&s.u.qk.Ql[rb * 40 + cc]);
            al[1] = ld_h2(&s.u.qk.Ql[(rb + 8) * 40 + cc]);
            al[2] = ld_h2(&s.u.qk.Ql[rb * 40 + cc + 8]);
            al[3] = ld_h2(&s.u.qk.Ql[(rb + 8) * 40 + cc + 8]);
            #pragma unroll
            for (int nt = 0; nt < 7; nt++) {
                const int nb = nt * 8 + rr;
                uint32_t bh[2], bl[2];
                bh[0] = ld_h2(&s.u.qk.Kh[nb * 40 + cc]);
                bh[1] = ld_h2(&s.u.qk.Kh[nb * 40 + cc + 8]);
                bl[0] = ld_h2(&s.u.qk.Kl[nb * 40 + cc]);
                bl[1] = ld_h2(&s.u.qk.Kl[nb * 40 + cc + 8]);
                mma_f16(acc[nt], ah, bh);
                mma_f16(acc[nt], ah, bl);
                mma_f16(acc[nt], al, bh);
            }
        }
        const int r0 = wm * 16 + rr;
        #pragma unroll
        for (int nt = 0; nt < 7; nt++) {
            const int c = nt * 8 + qoff;
            s.sc[r0 * 57 + c]           = acc[nt][0];
            s.sc[r0 * 57 + c + 1]       = acc[nt][1];
            s.sc[(r0 + 8) * 57 + c]     = acc[nt][2];
            s.sc[(r0 + 8) * 57 + c + 1] = acc[nt][3];
        }
    }
    __syncthreads();

    // ---- softmax (+bias), write P split fp16 ----
    const float* bias = &g_bias[h * (NTOK * NTOK)];
    for (int i = wm; i < NTOK; i += 4) {
        const int j2 = 32 + lane;
        const bool v2 = (j2 < NTOK);
        float s0 = s.sc[i * 57 + lane] + bias[i * 49 + lane];
        float s1 = v2 ? (s.sc[i * 57 + j2] + bias[i * 49 + j2]) : -3.0e38f;
        float mx = fmaxf(s0, s1);
        #pragma unroll
        for (int o = 16; o; o >>= 1) mx = fmaxf(mx, __shfl_xor_sync(0xffffffffu, mx, o));
        float p0 = expf(s0 - mx);
        float p1 = v2 ? expf(s1 - mx) : 0.f;
        float sum = p0 + p1;
        #pragma unroll
        for (int o = 16; o; o >>= 1) sum += __shfl_xor_sync(0xffffffffu, sum, o);
        float inv = 1.f / sum;
        p0 *= inv;
        p1 = v2 ? p1 * inv : 0.f;
        {
            __half hi = __float2half_rn(p0);
            __half lo = __float2half_rn(p0 - __half2float(hi));
            s.u.p.Ph[i * 72 + lane] = hi;
            s.u.p.Pl[i * 72 + lane] = lo;
            __half hi1 = __float2half_rn(p1);
            __half lo1 = __float2half_rn(p1 - __half2float(hi1));
            s.u.p.Ph[i * 72 + j2] = hi1;
            s.u.p.Pl[i * 72 + j2] = lo1;
        }
    }
    __syncthreads();

    // ---- PV ----
    {
        float acc[4][4];
        #pragma unroll
        for (int nt = 0; nt < 4; nt++)
            #pragma unroll
            for (int c = 0; c < 4; c++) acc[nt][c] = 0.f;

        #pragma unroll
        for (int kt = 0; kt < 64; kt += 16) {
            uint32_t ah[4], al[4];
            const int rb = wm * 16 + rr;
            const int cc = kt + qoff;
            ah[0] = ld_h2(&s.u.p.Ph[rb * 72 + cc]);
            ah[1] = ld_h2(&s.u.p.Ph[(rb + 8) * 72 + cc]);
            ah[2] = ld_h2(&s.u.p.Ph[rb * 72 + cc + 8]);
            ah[3] = ld_h2(&s.u.p.Ph[(rb + 8) * 72 + cc + 8]);
            al[0] = ld_h2(&s.u.p.Pl[rb * 72 + cc]);
            al[1] = ld_h2(&s.u.p.Pl[(rb + 8) * 72 + cc]);
            al[2] = ld_h2(&s.u.p.Pl[rb * 72 + cc + 8]);
            al[3] = ld_h2(&s.u.p.Pl[(rb + 8) * 72 + cc + 8]);
            #pragma unroll
            for (int nt = 0; nt < 4; nt++) {
                const int nb = nt * 8 + rr;
                uint32_t bh[2], bl[2];
                bh[0] = ld_h2(&s.Vth[nb * 72 + cc]);
                bh[1] = ld_h2(&s.Vth[nb * 72 + cc + 8]);
                bl[0] = ld_h2(&s.Vtl[nb * 72 + cc]);
                bl[1] = ld_h2(&s.Vtl[nb * 72 + cc + 8]);
                mma_f16(acc[nt], ah, bh);
                mma_f16(acc[nt], ah, bl);
                mma_f16(acc[nt], al, bh);
            }
        }
        const int r0 = wm * 16 + rr;
        #pragma unroll
        for (int nt = 0; nt < 4; nt++) {
            const int d = nt * 8 + qoff;
            if (r0 < NTOK) {
                float2 v = make_float2(acc[nt][0], acc[nt][1]);
                *reinterpret_cast<float2*>(&g_ao[((size_t)ww * NTOK + r0) * HID + h * DHEAD + d]) = v;
            }
            if (r0 + 8 < NTOK) {
                float2 v = make_float2(acc[nt][2], acc[nt][3]);
                *reinterpret_cast<float2*>(&g_ao[((size_t)ww * NTOK + r0 + 8) * HID + h * DHEAD + d]) = v;
            }
        }
    }
}

// ---------------- K3: output projection ----------------
__global__ void __launch_bounds__(256) fc_kernel(const float* __restrict__ fc_w,
                                                 const float* __restrict__ fc_b,
                                                 float* __restrict__ out) {
    __shared__ SmemU sm;
    float acc[2][6][4];
    #pragma unroll
    for (int a = 0; a < 2; a++)
        #pragma unroll
        for (int b = 0; b < 6; b++)
            #pragma unroll
            for (int c = 0; c < 4; c++) acc[a][b][c] = 0.f;

    const int n0 = blockIdx.x * 96;
    const int m0 = blockIdx.y * 128;
    run_gemm(g_ao, fc_w, m0, n0, &sm.g, acc);

    const int lane = threadIdx.x & 31, wid = threadIdx.x >> 5;
    const int wm = wid & 3, wn = wid >> 2;
    const int rr = lane >> 2, c2 = (lane & 3) << 1;
    #pragma unroll
    for (int mt = 0; mt < 2; mt++)
        #pragma unroll
        for (int nt = 0; nt < 6; nt++) {
            int row = m0 + wm * 32 + mt * 16 + rr;
            int col = n0 + wn * 48 + nt * 8 + c2;
            float b0 = fc_b[col], b1 = fc_b[col + 1];
            float2 v0 = make_float2(acc[mt][nt][0] + b0, acc[mt][nt][1] + b1);
            float2 v1 = make_float2(acc[mt][nt][2] + b0, acc[mt][nt][3] + b1);
            *reinterpret_cast<float2*>(&out[(size_t)row * 384 + col])       = v0;
            *reinterpret_cast<float2*>(&out[(size_t)(row + 8) * 384 + col]) = v1;
        }
}

// ---------------- launch ----------------
extern "C" void kernel_launch(void* const* d_in, const int* in_sizes, int n_in,
                              void* d_out, int out_size) {
    const float* x    = (const float*)d_in[0];
    const float* tbl  = (const float*)d_in[1];
    const float* qw   = (const float*)d_in[2];
    const float* qb   = (const float*)d_in[3];
    const float* fw   = (const float*)d_in[4];
    const float* fb   = (const float*)d_in[5];
    const int*   ridx = (const int*)d_in[6];
    float* out = (float*)d_out;

    bias_kernel<<<(NHEAD * NTOK * NTOK + 255) / 256, 256>>>(tbl, ridx);
    qkv_kernel<<<dim3(NHEAD, MTOT / 128), 256>>>(x, qw, qb);
    attn_kernel<<<NWIN * NHEAD, 128>>>();
    fc_kernel<<<dim3(HID / 96, MTOT / 128), 256>>>(fw, fb, out);
}

// round 15
// speedup vs baseline: 1.2892x; 1.0447x over previous
#include <cuda_runtime.h>
#include <cuda_fp16.h>
#include <cstdint>

// ---------------- problem constants ----------------
#define NWIN    4096
#define NTOK    49
#define HID     384
#define NHEAD   12
#define DHEAD   32
#define MTOT    (NWIN*NTOK)          // 200704
#define QSCALE  0.17677669529663687f // 32^-0.5

#define NBH     (NWIN*NHEAD)         // 49152
#define QK_STRIDE (49*40)
#define VT_STRIDE (32*72)

// ---------------- device scratch ----------------
__device__ __half g_qh[(size_t)NBH * QK_STRIDE];
__device__ __half g_ql[(size_t)NBH * QK_STRIDE];
__device__ __half g_kh[(size_t)NBH * QK_STRIDE];
__device__ __half g_kl[(size_t)NBH * QK_STRIDE];
__device__ __half g_vth[(size_t)NBH * VT_STRIDE];   // pads stay zero (.bss)
__device__ __half g_vtl[(size_t)NBH * VT_STRIDE];
__device__ float g_ao[(size_t)MTOT * HID];
__device__ float g_bias[NHEAD * NTOK * NTOK];

// ---------------- GEMM smem: A hi+lo, B hi only ----------------
struct SmemGemm {
    __half Ah[128 * 40];   // 10240 B
    __half Al[128 * 40];   // 10240 B
    __half Bh[96 * 40];    //  7680 B
};
union SmemU {
    SmemGemm g;
    float    c[128 * 96];  // 49152 B (C staging, qkv only)
};

// ---------------- helpers ----------------
__device__ __forceinline__ void mma_f16(float c[4], const uint32_t a[4], const uint32_t b[2]) {
    asm volatile(
        "mma.sync.aligned.m16n8k16.row.col.f32.f16.f16.f32 "
        "{%0,%1,%2,%3}, {%4,%5,%6,%7}, {%8,%9}, {%0,%1,%2,%3};\n"
        : "+f"(c[0]), "+f"(c[1]), "+f"(c[2]), "+f"(c[3])
        : "r"(a[0]), "r"(a[1]), "r"(a[2]), "r"(a[3]),
          "r"(b[0]), "r"(b[1]));
}

__device__ __forceinline__ void ldsm4(uint32_t r[4], uint32_t addr) {
    asm volatile("ldmatrix.sync.aligned.m8n8.x4.shared.b16 {%0,%1,%2,%3}, [%4];\n"
                 : "=r"(r[0]), "=r"(r[1]), "=r"(r[2]), "=r"(r[3]) : "r"(addr));
}

__device__ __forceinline__ uint32_t ld_h2(const __half* p) {
    return *reinterpret_cast<const uint32_t*>(p);
}

__device__ __forceinline__ void split_store(__half* hi, __half* lo, float a, float b) {
    __half2 h, l;
    h.x = __float2half_rn(a); l.x = __float2half_rn(a - __half2float(h.x));
    h.y = __float2half_rn(b); l.y = __float2half_rn(b - __half2float(h.y));
    *reinterpret_cast<__half2*>(hi) = h;
    *reinterpret_cast<__half2*>(lo) = l;
}

__device__ __forceinline__ void hi_store(__half* hi, float a, float b) {
    *reinterpret_cast<__half2*>(hi) = __floats2half2_rn(a, b);
}

__device__ __forceinline__ void cp16(uint32_t smem_addr, const void* gptr) {
    asm volatile("cp.async.cg.shared.global [%0], [%1], 16;\n"
                 :: "r"(smem_addr), "l"(gptr));
}

// ---------------- GEMM mainloop: C[128x96] = A*B^T, 4 warps, warp tile 32x96 ----------------
// 2-term split (A hi+lo, B hi). Fragment redundancy: A x1, B x4.
__device__ __forceinline__ void run_gemm(const float* __restrict__ A,
                                         const float* __restrict__ B,
                                         int m0, int n0,
                                         SmemGemm* sm, float acc[2][12][4]) {
    const int tid  = threadIdx.x;   // 0..127
    const int lane = tid & 31;
    const int wid  = tid >> 5;      // 0..3 (M group)
    const int lr   = tid >> 3;      // 0..15
    const int lc   = (tid & 7) << 2;

    const float* Abase = A + (size_t)(m0 + lr) * 384 + lc;
    const float* Bbase = B + (size_t)(n0 + lr) * 384 + lc;

    const uint32_t AhB = (uint32_t)__cvta_generic_to_shared(sm->Ah);
    const uint32_t AlB = (uint32_t)__cvta_generic_to_shared(sm->Al);
    const uint32_t BhB = (uint32_t)__cvta_generic_to_shared(sm->Bh);

    const int aRow = wid * 32 + (lane & 15);
    const int aCol = (lane >> 4) << 3;
    const int bRow = (lane & 7) + ((lane & 16) >> 1);   // + ntp*16
    const int bCol = lane & 8;

    for (int k0 = 0; k0 < 384; k0 += 32) {
        __syncthreads();
        #pragma unroll
        for (int p = 0; p < 8; p++) {
            int row = lr + p * 16;
            float4 v = *reinterpret_cast<const float4*>(Abase + (size_t)p * 16 * 384 + k0);
            split_store(&sm->Ah[row * 40 + lc],     &sm->Al[row * 40 + lc],     v.x, v.y);
            split_store(&sm->Ah[row * 40 + lc + 2], &sm->Al[row * 40 + lc + 2], v.z, v.w);
        }
        #pragma unroll
        for (int p = 0; p < 6; p++) {
            int row = lr + p * 16;
            float4 v = *reinterpret_cast<const float4*>(Bbase + (size_t)p * 16 * 384 + k0);
            hi_store(&sm->Bh[row * 40 + lc],     v.x, v.y);
            hi_store(&sm->Bh[row * 40 + lc + 2], v.z, v.w);
        }
        __syncthreads();

        #pragma unroll
        for (int ks = 0; ks < 32; ks += 16) {
            uint32_t ah[2][4], al[2][4], bh4[6][4];
            #pragma unroll
            for (int mt = 0; mt < 2; mt++) {
                const uint32_t aoff = (uint32_t)(((aRow + mt * 16) * 40 + ks + aCol) * 2);
                ldsm4(ah[mt], AhB + aoff);
                ldsm4(al[mt], AlB + aoff);
            }
            #pragma unroll
            for (int ntp = 0; ntp < 6; ntp++) {
                const uint32_t boff = (uint32_t)(((bRow + ntp * 16) * 40 + ks + bCol) * 2);
                ldsm4(bh4[ntp], BhB + boff);
            }
            #pragma unroll
            for (int mt = 0; mt < 2; mt++)
                #pragma unroll
                for (int nt = 0; nt < 12; nt++) {
                    const uint32_t* bh = &bh4[nt >> 1][(nt & 1) * 2];
                    mma_f16(acc[mt][nt], ah[mt], bh);
                    mma_f16(acc[mt][nt], al[mt], bh);
                }
        }
    }
}

// ---------------- K0: dense relative position bias ----------------
__global__ void bias_kernel(const float* __restrict__ table, const int* __restrict__ ridx) {
    int e = blockIdx.x * 256 + threadIdx.x;
    if (e < NHEAD * NTOK * NTOK) {
        int h = e / (NTOK * NTOK);
        int r = e - h * (NTOK * NTOK);
        g_bias[e] = table[ridx[r] * NHEAD + h];
    }
}

// ---------------- K1: QKV projection + split scatter ----------------
__global__ void __launch_bounds__(128) qkv_kernel(const float* __restrict__ x,
                                                  const float* __restrict__ qkv_w,
                                                  const float* __restrict__ qkv_b) {
    __shared__ SmemU sm;
    float acc[2][12][4];
    #pragma unroll
    for (int a = 0; a < 2; a++)
        #pragma unroll
        for (int b = 0; b < 12; b++)
            #pragma unroll
            for (int c = 0; c < 4; c++) acc[a][b][c] = 0.f;

    const int n0 = blockIdx.x * 96;
    const int m0 = blockIdx.y * 128;
    run_gemm(x, qkv_w, m0, n0, &sm.g, acc);
    __syncthreads();

    const int lane = threadIdx.x & 31, wid = threadIdx.x >> 5;
    const int rr = lane >> 2, c2 = (lane & 3) << 1;
    #pragma unroll
    for (int mt = 0; mt < 2; mt++)
        #pragma unroll
        for (int nt = 0; nt < 12; nt++) {
            int row = wid * 32 + mt * 16 + rr;
            int col = nt * 8 + c2;
            sm.c[row * 96 + col]           = acc[mt][nt][0];
            sm.c[row * 96 + col + 1]       = acc[mt][nt][1];
            sm.c[(row + 8) * 96 + col]     = acc[mt][nt][2];
            sm.c[(row + 8) * 96 + col + 1] = acc[mt][nt][3];
        }
    __syncthreads();

    const int h = blockIdx.x;
    // q,k: split hi/lo, planar layout [w,h][t*40+dd]
    for (int e = threadIdx.x; e < 128 * 64; e += 128) {
        int dd  = e & 31;
        int sp  = (e >> 5) & 1;
        int row = e >> 6;
        int col = dd * 3 + sp;
        float val = sm.c[row * 96 + col] + qkv_b[n0 + col];
        if (sp == 0) val *= QSCALE;
        __half hi = __float2half_rn(val);
        __half lo = __float2half_rn(val - __half2float(hi));
        int m = m0 + row;
        int ww = m / 49;
        int t  = m - ww * 49;
        size_t o = (size_t)(ww * NHEAD + h) * QK_STRIDE + t * 40 + dd;
        if (sp == 0) { g_qh[o] = hi; g_ql[o] = lo; }
        else         { g_kh[o] = hi; g_kl[o] = lo; }
    }
    // v: transposed layout [w,h][dd*72+t]
    for (int e = threadIdx.x; e < 128 * 32; e += 128) {
        int row = e & 127;
        int dd  = e >> 7;
        int col = dd * 3 + 2;
        float val = sm.c[row * 96 + col] + qkv_b[n0 + col];
        __half hi = __float2half_rn(val);
        __half lo = __float2half_rn(val - __half2float(hi));
        int m = m0 + row;
        int ww = m / 49;
        int t  = m - ww * 49;
        size_t o = (size_t)(ww * NHEAD + h) * VT_STRIDE + dd * 72 + t;
        g_vth[o] = hi;
        g_vtl[o] = lo;
    }
}

// ---------------- K2: attention (3-term split MMA, __expf softmax) ----------------
struct AttnSmem {
    union {
        struct {
            __half Qh[64 * 40];
            __half Ql[64 * 40];
            __half Kh[64 * 40];
            __half Kl[64 * 40];
        } qk;
        struct {
            __half Ph[64 * 72];
            __half Pl[64 * 72];
        } p;
    } u;
    __half Vth[32 * 72];
    __half Vtl[32 * 72];
    float  sc[64 * 57];
};

__global__ void __launch_bounds__(128) attn_kernel() {
    const int bid = blockIdx.x;        // ww*NHEAD + h
    const int h   = bid % NHEAD;
    const int ww  = bid / NHEAD;

    __shared__ AttnSmem s;

    const int tid = threadIdx.x, lane = tid & 31, wm = tid >> 5;
    const int rr  = lane >> 2;
    const int qoff = (lane & 3) << 1;

    {
        const uint32_t smQ = (uint32_t)__cvta_generic_to_shared(s.u.qk.Qh);
        const uint32_t smV = (uint32_t)__cvta_generic_to_shared(s.Vth);
        const char* gqh = (const char*)g_qh + (size_t)bid * (QK_STRIDE * 2);
        const char* gql = (const char*)g_ql + (size_t)bid * (QK_STRIDE * 2);
        const char* gkh = (const char*)g_kh + (size_t)bid * (QK_STRIDE * 2);
        const char* gkl = (const char*)g_kl + (size_t)bid * (QK_STRIDE * 2);
        const char* gvh = (const char*)g_vth + (size_t)bid * (VT_STRIDE * 2);
        const char* gvl = (const char*)g_vtl + (size_t)bid * (VT_STRIDE * 2);
        for (int e = tid; e < 245; e += 128) {
            cp16(smQ + e * 16,         gqh + e * 16);
            cp16(smQ + 5120 + e * 16,  gql + e * 16);
            cp16(smQ + 10240 + e * 16, gkh + e * 16);
            cp16(smQ + 15360 + e * 16, gkl + e * 16);
        }
        for (int e = tid; e < 288; e += 128) {
            cp16(smV + e * 16,        gvh + e * 16);
            cp16(smV + 4608 + e * 16, gvl + e * 16);
        }
        asm volatile("cp.async.commit_group;\n");
        asm volatile("cp.async.wait_group 0;\n" ::: "memory");
    }
    __syncthreads();

    // ---- scores ----
    {
        float acc[7][4];
        #pragma unroll
        for (int nt = 0; nt < 7; nt++)
            #pragma unroll
            for (int c = 0; c < 4; c++) acc[nt][c] = 0.f;

        #pragma unroll
        for (int kt = 0; kt < 32; kt += 16) {
            uint32_t ah[4], al[4];
            const int rb = wm * 16 + rr;
            const int cc = kt + qoff;
            ah[0] = ld_h2(&s.u.qk.Qh[rb * 40 + cc]);
            ah[1] = ld_h2(&s.u.qk.Qh[(rb + 8) * 40 + cc]);
            ah[2] = ld_h2(&s.u.qk.Qh[rb * 40 + cc + 8]);
            ah[3] = ld_h2(&s.u.qk.Qh[(rb + 8) * 40 + cc + 8]);
            al[0] = ld_h2(&s.u.qk.Ql[rb * 40 + cc]);
            al[1] = ld_h2(&s.u.qk.Ql[(rb + 8) * 40 + cc]);
            al[2] = ld_h2(&s.u.qk.Ql[rb * 40 + cc + 8]);
            al[3] = ld_h2(&s.u.qk.Ql[(rb + 8) * 40 + cc + 8]);
            #pragma unroll
            for (int nt = 0; nt < 7; nt++) {
                const int nb = nt * 8 + rr;
                uint32_t bh[2], bl[2];
                bh[0] = ld_h2(&s.u.qk.Kh[nb * 40 + cc]);
                bh[1] = ld_h2(&s.u.qk.Kh[nb * 40 + cc + 8]);
                bl[0] = ld_h2(&s.u.qk.Kl[nb * 40 + cc]);
                bl[1] = ld_h2(&s.u.qk.Kl[nb * 40 + cc + 8]);
                mma_f16(acc[nt], ah, bh);
                mma_f16(acc[nt], ah, bl);
                mma_f16(acc[nt], al, bh);
            }
        }
        const int r0 = wm * 16 + rr;
        #pragma unroll
        for (int nt = 0; nt < 7; nt++) {
            const int c = nt * 8 + qoff;
            s.sc[r0 * 57 + c]           = acc[nt][0];
            s.sc[r0 * 57 + c + 1]       = acc[nt][1];
            s.sc[(r0 + 8) * 57 + c]     = acc[nt][2];
            s.sc[(r0 + 8) * 57 + c + 1] = acc[nt][3];
        }
    }
    __syncthreads();

    // ---- softmax (+bias), write P split fp16 ----
    const float* bias = &g_bias[h * (NTOK * NTOK)];
    for (int i = wm; i < NTOK; i += 4) {
        const int j2 = 32 + lane;
        const bool v2 = (j2 < NTOK);
        float s0 = s.sc[i * 57 + lane] + bias[i * 49 + lane];
        float s1 = v2 ? (s.sc[i * 57 + j2] + bias[i * 49 + j2]) : -3.0e38f;
        float mx = fmaxf(s0, s1);
        #pragma unroll
        for (int o = 16; o; o >>= 1) mx = fmaxf(mx, __shfl_xor_sync(0xffffffffu, mx, o));
        float p0 = __expf(s0 - mx);
        float p1 = v2 ? __expf(s1 - mx) : 0.f;
        float sum = p0 + p1;
        #pragma unroll
        for (int o = 16; o; o >>= 1) sum += __shfl_xor_sync(0xffffffffu, sum, o);
        float inv = 1.f / sum;
        p0 *= inv;
        p1 = v2 ? p1 * inv : 0.f;
        {
            __half hi = __float2half_rn(p0);
            __half lo = __float2half_rn(p0 - __half2float(hi));
            s.u.p.Ph[i * 72 + lane] = hi;
            s.u.p.Pl[i * 72 + lane] = lo;
            __half hi1 = __float2half_rn(p1);
            __half lo1 = __float2half_rn(p1 - __half2float(hi1));
            s.u.p.Ph[i * 72 + j2] = hi1;
            s.u.p.Pl[i * 72 + j2] = lo1;
        }
    }
    __syncthreads();

    // ---- PV ----
    {
        float acc[4][4];
        #pragma unroll
        for (int nt = 0; nt < 4; nt++)
            #pragma unroll
            for (int c = 0; c < 4; c++) acc[nt][c] = 0.f;

        #pragma unroll
        for (int kt = 0; kt < 64; kt += 16) {
            uint32_t ah[4], al[4];
            const int rb = wm * 16 + rr;
            const int cc = kt + qoff;
            ah[0] = ld_h2(&s.u.p.Ph[rb * 72 + cc]);
            ah[1] = ld_h2(&s.u.p.Ph[(rb + 8) * 72 + cc]);
            ah[2] = ld_h2(&s.u.p.Ph[rb * 72 + cc + 8]);
            ah[3] = ld_h2(&s.u.p.Ph[(rb + 8) * 72 + cc + 8]);
            al[0] = ld_h2(&s.u.p.Pl[rb * 72 + cc]);
            al[1] = ld_h2(&s.u.p.Pl[(rb + 8) * 72 + cc]);
            al[2] = ld_h2(&s.u.p.Pl[rb * 72 + cc + 8]);
            al[3] = ld_h2(&s.u.p.Pl[(rb + 8) * 72 + cc + 8]);
            #pragma unroll
            for (int nt = 0; nt < 4; nt++) {
                const int nb = nt * 8 + rr;
                uint32_t bh[2], bl[2];
                bh[0] = ld_h2(&s.Vth[nb * 72 + cc]);
                bh[1] = ld_h2(&s.Vth[nb * 72 + cc + 8]);
                bl[0] = ld_h2(&s.Vtl[nb * 72 + cc]);
                bl[1] = ld_h2(&s.Vtl[nb * 72 + cc + 8]);
                mma_f16(acc[nt], ah, bh);
                mma_f16(acc[nt], ah, bl);
                mma_f16(acc[nt], al, bh);
            }
        }
        const int r0 = wm * 16 + rr;
        #pragma unroll
        for (int nt = 0; nt < 4; nt++) {
            const int d = nt * 8 + qoff;
            if (r0 < NTOK) {
                float2 v = make_float2(acc[nt][0], acc[nt][1]);
                *reinterpret_cast<float2*>(&g_ao[((size_t)ww * NTOK + r0) * HID + h * DHEAD + d]) = v;
            }
            if (r0 + 8 < NTOK) {
                float2 v = make_float2(acc[nt][2], acc[nt][3]);
                *reinterpret_cast<float2*>(&g_ao[((size_t)ww * NTOK + r0 + 8) * HID + h * DHEAD + d]) = v;
            }
        }
    }
}

// ---------------- K3: output projection ----------------
__global__ void __launch_bounds__(128) fc_kernel(const float* __restrict__ fc_w,
                                                 const float* __restrict__ fc_b,
                                                 float* __restrict__ out) {
    __shared__ SmemGemm sm;
    float acc[2][12][4];
    #pragma unroll
    for (int a = 0; a < 2; a++)
        #pragma unroll
        for (int b = 0; b < 12; b++)
            #pragma unroll
            for (int c = 0; c < 4; c++) acc[a][b][c] = 0.f;

    const int n0 = blockIdx.x * 96;
    const int m0 = blockIdx.y * 128;
    run_gemm(g_ao, fc_w, m0, n0, &sm, acc);

    const int lane = threadIdx.x & 31, wid = threadIdx.x >> 5;
    const int rr = lane >> 2, c2 = (lane & 3) << 1;
    #pragma unroll
    for (int mt = 0; mt < 2; mt++)
        #pragma unroll
        for (int nt = 0; nt < 12; nt++) {
            int row = m0 + wid * 32 + mt * 16 + rr;
            int col = n0 + nt * 8 + c2;
            float b0 = fc_b[col], b1 = fc_b[col + 1];
            float2 v0 = make_float2(acc[mt][nt][0] + b0, acc[mt][nt][1] + b1);
            float2 v1 = make_float2(acc[mt][nt][2] + b0, acc[mt][nt][3] + b1);
            *reinterpret_cast<float2*>(&out[(size_t)row * 384 + col])       = v0;
            *reinterpret_cast<float2*>(&out[(size_t)(row + 8) * 384 + col]) = v1;
        }
}

// ---------------- launch ----------------
extern "C" void kernel_launch(void* const* d_in, const int* in_sizes, int n_in,
                              void* d_out, int out_size) {
    const float* x    = (const float*)d_in[0];
    const float* tbl  = (const float*)d_in[1];
    const float* qw   = (const float*)d_in[2];
    const float* qb   = (const float*)d_in[3];
    const float* fw   = (const float*)d_in[4];
    const float* fb   = (const float*)d_in[5];
    const int*   ridx = (const int*)d_in[6];
    float* out = (float*)d_out;

    bias_kernel<<<(NHEAD * NTOK * NTOK + 255) / 256, 256>>>(tbl, ridx);
    qkv_kernel<<<dim3(NHEAD, MTOT / 128), 128>>>(x, qw, qb);
    attn_kernel<<<NWIN * NHEAD, 128>>>();
    fc_kernel<<<dim3(HID / 96, MTOT / 128), 128>>>(fw, fb, out);
}